// round 2
// baseline (speedup 1.0000x reference)
#include <cuda_runtime.h>
#include <cuda_bf16.h>
#include <math.h>

// ---------------------------------------------------------------------------
// TransformerEncoderBlock: B=4, S=2048, D=1024, H=16, Dk=64, Dff=4096, fp32.
// Round 2: fp32 SIMT baseline with double-buffered SGEMM mainloop.
// ---------------------------------------------------------------------------

#define BATCH   4
#define SEQ     2048
#define DMODEL  1024
#define NHEADS  16
#define DK      64
#define DFF     4096
#define MROWS   (BATCH * SEQ)   // 8192

// Scratch (no allocations allowed -> __device__ globals)
__device__ float g_h  [MROWS * DMODEL];
__device__ float g_q  [MROWS * DMODEL];
__device__ float g_k  [MROWS * DMODEL];
__device__ float g_v  [MROWS * DMODEL];
__device__ float g_ctx[MROWS * DMODEL];
__device__ float g_x1 [MROWS * DMODEL];
__device__ float g_h2 [MROWS * DMODEL];
__device__ float g_ffn[MROWS * DFF];

// ---------------------------------------------------------------------------
// LayerNorm: one block per row of 1024, 256 threads, each thread one float4.
// ---------------------------------------------------------------------------
__global__ __launch_bounds__(256) void ln_kernel(
    const float* __restrict__ x, const float* __restrict__ gamma,
    const float* __restrict__ beta, float* __restrict__ out)
{
    int row = blockIdx.x;
    int tid = threadIdx.x;
    const float4* xr = (const float4*)(x + (size_t)row * DMODEL);
    float4 v = xr[tid];

    __shared__ float red[256];
    float s = v.x + v.y + v.z + v.w;
    red[tid] = s; __syncthreads();
    #pragma unroll
    for (int off = 128; off > 0; off >>= 1) {
        if (tid < off) red[tid] += red[tid + off];
        __syncthreads();
    }
    float mu = red[0] * (1.0f / DMODEL);
    __syncthreads();

    float dx0 = v.x - mu, dx1 = v.y - mu, dx2 = v.z - mu, dx3 = v.w - mu;
    float s2 = dx0*dx0 + dx1*dx1 + dx2*dx2 + dx3*dx3;
    red[tid] = s2; __syncthreads();
    #pragma unroll
    for (int off = 128; off > 0; off >>= 1) {
        if (tid < off) red[tid] += red[tid + off];
        __syncthreads();
    }
    float var = red[0] * (1.0f / DMODEL);
    float rs = rsqrtf(var + 1e-5f);

    float4 g4 = ((const float4*)gamma)[tid];
    float4 b4 = ((const float4*)beta)[tid];
    float4 o;
    o.x = dx0 * rs * g4.x + b4.x;
    o.y = dx1 * rs * g4.y + b4.y;
    o.z = dx2 * rs * g4.z + b4.z;
    o.w = dx3 * rs * g4.w + b4.w;
    ((float4*)(out + (size_t)row * DMODEL))[tid] = o;
}

// ---------------------------------------------------------------------------
// SGEMM: C[M,N] = A[M,K] @ B[K,N] + bias (+ residual | + gelu)
// 128x128 block tile, BK=8, 256 threads, 8x8 per-thread microtile.
// Double-buffered smem: one __syncthreads per k-step, LDG overlapped.
// EPI: 0 = bias, 1 = bias + residual, 2 = bias + exact gelu
// M % 128 == 0, N % 128 == 0, K % 8 == 0 (holds for all calls).
// ---------------------------------------------------------------------------
__device__ __forceinline__ float gelu_exact(float x) {
    return 0.5f * x * (1.0f + erff(x * 0.70710678118654752f));
}

template<int EPI>
__global__ __launch_bounds__(256) void sgemm_kernel(
    const float* __restrict__ A, const float* __restrict__ B,
    const float* __restrict__ bias, const float* __restrict__ R,
    float* __restrict__ C, int M, int N, int K)
{
    __shared__ float As[2][8][132];   // transposed A tile, padded
    __shared__ float Bs[2][8][128];

    int tid = threadIdx.x;
    int bm = blockIdx.y * 128;
    int bn = blockIdx.x * 128;

    // global-load assignments
    int arow = tid >> 1;            // 0..127
    int acol = (tid & 1) << 2;      // 0 or 4
    int brow = tid >> 5;            // 0..7
    int bcol = (tid & 31) << 2;     // 0..124

    // compute assignments: 16x16 thread grid, 8x8 each
    int tx = tid & 15;
    int ty = tid >> 4;

    float acc[8][8];
    #pragma unroll
    for (int i = 0; i < 8; i++)
        #pragma unroll
        for (int j = 0; j < 8; j++) acc[i][j] = 0.0f;

    const float* Aptr = A + (size_t)(bm + arow) * K + acol;
    const float* Bptr = B + (size_t)brow * N + bn + bcol;

    int nk = K >> 3;

    // prologue: load tile 0 into buffer 0
    {
        float4 av = *(const float4*)(Aptr);
        float4 bv = *(const float4*)(Bptr);
        As[0][acol + 0][arow] = av.x;
        As[0][acol + 1][arow] = av.y;
        As[0][acol + 2][arow] = av.z;
        As[0][acol + 3][arow] = av.w;
        *(float4*)&Bs[0][brow][bcol] = bv;
    }
    __syncthreads();

    for (int t = 0; t < nk; t++) {
        int cur = t & 1;
        int nxt = cur ^ 1;

        float4 av, bv;
        bool has_next = (t + 1 < nk);
        if (has_next) {
            int k0 = (t + 1) << 3;
            av = *(const float4*)(Aptr + k0);
            bv = *(const float4*)(Bptr + (size_t)k0 * N);
        }

        #pragma unroll
        for (int kk = 0; kk < 8; kk++) {
            float4 a0 = *(const float4*)&As[cur][kk][ty * 8];
            float4 a1 = *(const float4*)&As[cur][kk][ty * 8 + 4];
            float4 b0 = *(const float4*)&Bs[cur][kk][tx * 8];
            float4 b1 = *(const float4*)&Bs[cur][kk][tx * 8 + 4];
            float ar[8] = {a0.x, a0.y, a0.z, a0.w, a1.x, a1.y, a1.z, a1.w};
            float br[8] = {b0.x, b0.y, b0.z, b0.w, b1.x, b1.y, b1.z, b1.w};
            #pragma unroll
            for (int i = 0; i < 8; i++)
                #pragma unroll
                for (int j = 0; j < 8; j++)
                    acc[i][j] = fmaf(ar[i], br[j], acc[i][j]);
        }

        if (has_next) {
            As[nxt][acol + 0][arow] = av.x;
            As[nxt][acol + 1][arow] = av.y;
            As[nxt][acol + 2][arow] = av.z;
            As[nxt][acol + 3][arow] = av.w;
            *(float4*)&Bs[nxt][brow][bcol] = bv;
            __syncthreads();
        }
    }

    // epilogue
    int crow = bm + ty * 8;
    int ccol = bn + tx * 8;
    float4 bia0 = *(const float4*)&bias[ccol];
    float4 bia1 = *(const float4*)&bias[ccol + 4];
    float bb[8] = {bia0.x, bia0.y, bia0.z, bia0.w, bia1.x, bia1.y, bia1.z, bia1.w};

    #pragma unroll
    for (int i = 0; i < 8; i++) {
        size_t off = (size_t)(crow + i) * N + ccol;
        float vals[8];
        #pragma unroll
        for (int j = 0; j < 8; j++) vals[j] = acc[i][j] + bb[j];
        if (EPI == 1) {
            float4 r0 = *(const float4*)(R + off);
            float4 r1 = *(const float4*)(R + off + 4);
            vals[0] += r0.x; vals[1] += r0.y; vals[2] += r0.z; vals[3] += r0.w;
            vals[4] += r1.x; vals[5] += r1.y; vals[6] += r1.z; vals[7] += r1.w;
        }
        if (EPI == 2) {
            #pragma unroll
            for (int j = 0; j < 8; j++) vals[j] = gelu_exact(vals[j]);
        }
        float4 o0 = make_float4(vals[0], vals[1], vals[2], vals[3]);
        float4 o1 = make_float4(vals[4], vals[5], vals[6], vals[7]);
        *(float4*)(C + off) = o0;
        *(float4*)(C + off + 4) = o1;
    }
}

// ---------------------------------------------------------------------------
// Flash-style attention. Q/K/V stored row-major [B*S, H*DK]; head slice is
// contiguous DK=64 floats. Block = (qtile, h, b); 64 threads, 1 per query.
// Online softmax in chunks of 16 keys. mask[b, key] == 0 -> -inf.
// ---------------------------------------------------------------------------
__global__ __launch_bounds__(64) void attn_kernel(
    const float* __restrict__ Q, const float* __restrict__ K,
    const float* __restrict__ V, const int* __restrict__ mask,
    float* __restrict__ O)
{
    int b  = blockIdx.z;
    int h  = blockIdx.y;
    int qt = blockIdx.x;
    int tid = threadIdx.x;            // 0..63
    int qi = qt * 64 + tid;

    const float* qptr = Q + ((size_t)(b * SEQ + qi) * DMODEL) + h * DK;
    float qreg[DK];
    #pragma unroll
    for (int d4 = 0; d4 < 16; d4++) {
        float4 t = ((const float4*)qptr)[d4];
        qreg[d4*4+0] = t.x; qreg[d4*4+1] = t.y;
        qreg[d4*4+2] = t.z; qreg[d4*4+3] = t.w;
    }

    __shared__ float Ks[64][DK];
    __shared__ float Vs[64][DK];
    __shared__ int   ms[64];

    float m = -1e30f, l = 0.0f;
    float o[DK];
    #pragma unroll
    for (int d = 0; d < DK; d++) o[d] = 0.0f;

    for (int kt = 0; kt < SEQ / 64; kt++) {
        int kj = kt * 64 + tid;
        const float* kptr = K + ((size_t)(b * SEQ + kj) * DMODEL) + h * DK;
        const float* vptr = V + ((size_t)(b * SEQ + kj) * DMODEL) + h * DK;
        __syncthreads();
        #pragma unroll
        for (int d4 = 0; d4 < 16; d4++) {
            ((float4*)Ks[tid])[d4] = ((const float4*)kptr)[d4];
            ((float4*)Vs[tid])[d4] = ((const float4*)vptr)[d4];
        }
        ms[tid] = mask[b * SEQ + kj];
        __syncthreads();

        #pragma unroll 1
        for (int j0 = 0; j0 < 64; j0 += 16) {
            float sc[16];
            #pragma unroll
            for (int jj = 0; jj < 16; jj++) {
                const float4* kr = (const float4*)Ks[j0 + jj];
                float s0 = 0.f, s1 = 0.f, s2 = 0.f, s3 = 0.f;
                #pragma unroll
                for (int d4 = 0; d4 < 16; d4++) {
                    float4 kv = kr[d4];
                    s0 = fmaf(qreg[d4*4+0], kv.x, s0);
                    s1 = fmaf(qreg[d4*4+1], kv.y, s1);
                    s2 = fmaf(qreg[d4*4+2], kv.z, s2);
                    s3 = fmaf(qreg[d4*4+3], kv.w, s3);
                }
                float s = ((s0 + s1) + (s2 + s3)) * 0.125f;  // 1/sqrt(64)
                sc[jj] = (ms[j0 + jj] != 0) ? s : -1e30f;
            }
            float tmax = m;
            #pragma unroll
            for (int jj = 0; jj < 16; jj++) tmax = fmaxf(tmax, sc[jj]);
            float scale = __expf(m - tmax);
            m = tmax;
            l *= scale;
            #pragma unroll
            for (int d = 0; d < DK; d++) o[d] *= scale;
            #pragma unroll
            for (int jj = 0; jj < 16; jj++) {
                float p = __expf(sc[jj] - m);
                l += p;
                const float4* vr = (const float4*)Vs[j0 + jj];
                #pragma unroll
                for (int d4 = 0; d4 < 16; d4++) {
                    float4 vv = vr[d4];
                    o[d4*4+0] = fmaf(p, vv.x, o[d4*4+0]);
                    o[d4*4+1] = fmaf(p, vv.y, o[d4*4+1]);
                    o[d4*4+2] = fmaf(p, vv.z, o[d4*4+2]);
                    o[d4*4+3] = fmaf(p, vv.w, o[d4*4+3]);
                }
            }
        }
    }

    float inv = 1.0f / l;
    float* optr = O + ((size_t)(b * SEQ + qi) * DMODEL) + h * DK;
    #pragma unroll
    for (int d4 = 0; d4 < 16; d4++) {
        float4 t;
        t.x = o[d4*4+0] * inv; t.y = o[d4*4+1] * inv;
        t.z = o[d4*4+2] * inv; t.w = o[d4*4+3] * inv;
        ((float4*)optr)[d4] = t;
    }
}

// ---------------------------------------------------------------------------
// Host launch
// ---------------------------------------------------------------------------
extern "C" void kernel_launch(void* const* d_in, const int* in_sizes, int n_in,
                              void* d_out, int out_size)
{
    const float* x     = (const float*)d_in[0];
    const int*   mask  = (const int*)  d_in[1];
    const float* Wq    = (const float*)d_in[2];
    const float* bq    = (const float*)d_in[3];
    const float* Wk    = (const float*)d_in[4];
    const float* bk    = (const float*)d_in[5];
    const float* Wv    = (const float*)d_in[6];
    const float* bv    = (const float*)d_in[7];
    const float* Wo    = (const float*)d_in[8];
    const float* bo    = (const float*)d_in[9];
    const float* W1    = (const float*)d_in[10];
    const float* b1    = (const float*)d_in[11];
    const float* W2    = (const float*)d_in[12];
    const float* b2    = (const float*)d_in[13];
    const float* ln1_g = (const float*)d_in[14];
    const float* ln1_b = (const float*)d_in[15];
    const float* ln2_g = (const float*)d_in[16];
    const float* ln2_b = (const float*)d_in[17];
    float* out = (float*)d_out;

    float *h, *qb, *kb, *vb, *ctx, *x1, *h2, *ffn;
    cudaGetSymbolAddress((void**)&h,   g_h);
    cudaGetSymbolAddress((void**)&qb,  g_q);
    cudaGetSymbolAddress((void**)&kb,  g_k);
    cudaGetSymbolAddress((void**)&vb,  g_v);
    cudaGetSymbolAddress((void**)&ctx, g_ctx);
    cudaGetSymbolAddress((void**)&x1,  g_x1);
    cudaGetSymbolAddress((void**)&h2,  g_h2);
    cudaGetSymbolAddress((void**)&ffn, g_ffn);

    // 1) LN1
    ln_kernel<<<MROWS, 256>>>(x, ln1_g, ln1_b, h);

    // 2) QKV projections
    dim3 gP(DMODEL / 128, MROWS / 128);
    sgemm_kernel<0><<<gP, 256>>>(h, Wq, bq, nullptr, qb, MROWS, DMODEL, DMODEL);
    sgemm_kernel<0><<<gP, 256>>>(h, Wk, bk, nullptr, kb, MROWS, DMODEL, DMODEL);
    sgemm_kernel<0><<<gP, 256>>>(h, Wv, bv, nullptr, vb, MROWS, DMODEL, DMODEL);

    // 3) attention
    dim3 gA(SEQ / 64, NHEADS, BATCH);
    attn_kernel<<<gA, 64>>>(qb, kb, vb, mask, ctx);

    // 4) output projection + residual
    sgemm_kernel<1><<<gP, 256>>>(ctx, Wo, bo, x, x1, MROWS, DMODEL, DMODEL);

    // 5) LN2
    ln_kernel<<<MROWS, 256>>>(x1, ln2_g, ln2_b, h2);

    // 6) FFN up + GELU
    dim3 gF1(DFF / 128, MROWS / 128);
    sgemm_kernel<2><<<gF1, 256>>>(h2, W1, b1, nullptr, ffn, MROWS, DFF, DMODEL);

    // 7) FFN down + residual -> out
    dim3 gF2(DMODEL / 128, MROWS / 128);
    sgemm_kernel<1><<<gF2, 256>>>(ffn, W2, b2, x1, out, MROWS, DMODEL, DFF);
}

// round 3
// speedup vs baseline: 1.5022x; 1.5022x over previous
#include <cuda_runtime.h>
#include <cuda_bf16.h>
#include <math.h>

// ---------------------------------------------------------------------------
// TransformerEncoderBlock: B=4, S=2048, D=1024, H=16, Dk=64, Dff=4096, fp32.
// Round 3: all GEMMs on tensor cores via bf16 hi/lo split (3-term mma.sync),
// cp.async double-buffered pipeline. Attention remains scalar fp32.
// ---------------------------------------------------------------------------

#define BATCH   4
#define SEQ     2048
#define DMODEL  1024
#define NHEADS  16
#define DK      64
#define DFF     4096
#define MROWS   (BATCH * SEQ)   // 8192

#define BK      16
#define LDS_K   24              // BK + 8 pad (conflict-free fragment LDS)

// ---------------- scratch (__device__ globals; no allocs allowed) ----------
__device__ float g_q [MROWS * DMODEL];
__device__ float g_k [MROWS * DMODEL];
__device__ float g_v [MROWS * DMODEL];
__device__ float g_x1[MROWS * DMODEL];

__device__ __align__(16) __nv_bfloat16 g_hh  [MROWS * DMODEL];
__device__ __align__(16) __nv_bfloat16 g_hl  [MROWS * DMODEL];
__device__ __align__(16) __nv_bfloat16 g_ctxh[MROWS * DMODEL];
__device__ __align__(16) __nv_bfloat16 g_ctxl[MROWS * DMODEL];
__device__ __align__(16) __nv_bfloat16 g_h2h [MROWS * DMODEL];
__device__ __align__(16) __nv_bfloat16 g_h2l [MROWS * DMODEL];
__device__ __align__(16) __nv_bfloat16 g_ffnh[MROWS * DFF];
__device__ __align__(16) __nv_bfloat16 g_ffnl[MROWS * DFF];

__device__ __align__(16) __nv_bfloat16 g_wqh[DMODEL*DMODEL], g_wql[DMODEL*DMODEL];
__device__ __align__(16) __nv_bfloat16 g_wkh[DMODEL*DMODEL], g_wkl[DMODEL*DMODEL];
__device__ __align__(16) __nv_bfloat16 g_wvh[DMODEL*DMODEL], g_wvl[DMODEL*DMODEL];
__device__ __align__(16) __nv_bfloat16 g_woh[DMODEL*DMODEL], g_wol[DMODEL*DMODEL];
__device__ __align__(16) __nv_bfloat16 g_w1h[DFF*DMODEL],    g_w1l[DFF*DMODEL];   // [N=4096][K=1024]
__device__ __align__(16) __nv_bfloat16 g_w2h[DMODEL*DFF],    g_w2l[DMODEL*DFF];   // [N=1024][K=4096]

// ---------------------------------------------------------------------------
__device__ __forceinline__ void split_bf16(float v, __nv_bfloat16& hi, __nv_bfloat16& lo) {
    hi = __float2bfloat16(v);
    lo = __float2bfloat16(v - __bfloat162float(hi));
}

__device__ __forceinline__ float gelu_exact(float x) {
    return 0.5f * x * (1.0f + erff(x * 0.70710678118654752f));
}

__device__ __forceinline__ void cp16(const void* dst_smem, const void* src) {
    unsigned s = (unsigned)__cvta_generic_to_shared(dst_smem);
    asm volatile("cp.async.cg.shared.global [%0], [%1], 16;\n" :: "r"(s), "l"(src));
}

__device__ __forceinline__ void mma_bf16(float* c, const unsigned* a, const unsigned* b) {
    asm volatile(
        "mma.sync.aligned.m16n8k16.row.col.f32.bf16.bf16.f32 "
        "{%0,%1,%2,%3}, {%4,%5,%6,%7}, {%8,%9}, {%0,%1,%2,%3};\n"
        : "+f"(c[0]), "+f"(c[1]), "+f"(c[2]), "+f"(c[3])
        : "r"(a[0]), "r"(a[1]), "r"(a[2]), "r"(a[3]), "r"(b[0]), "r"(b[1]));
}

// ---------------------------------------------------------------------------
// Weight split + transpose:  W[K][N] fp32  ->  Th/Tl[N][K] bf16
// ---------------------------------------------------------------------------
__global__ __launch_bounds__(256) void wsplit_kernel(
    const float* __restrict__ W, __nv_bfloat16* __restrict__ Th,
    __nv_bfloat16* __restrict__ Tl, int K, int N)
{
    __shared__ float tile[32][33];
    int n0 = blockIdx.x * 32, k0 = blockIdx.y * 32;
    int tx = threadIdx.x & 31;
    int ty = threadIdx.x >> 5;   // 0..7
    #pragma unroll
    for (int i = 0; i < 32; i += 8)
        tile[ty + i][tx] = W[(size_t)(k0 + ty + i) * N + n0 + tx];
    __syncthreads();
    #pragma unroll
    for (int i = 0; i < 32; i += 8) {
        float v = tile[tx][ty + i];
        __nv_bfloat16 hi, lo; split_bf16(v, hi, lo);
        size_t o = (size_t)(n0 + ty + i) * K + k0 + tx;
        Th[o] = hi; Tl[o] = lo;
    }
}

// ---------------------------------------------------------------------------
// LayerNorm -> bf16 hi/lo outputs. One block per row, 256 threads.
// ---------------------------------------------------------------------------
__global__ __launch_bounds__(256) void ln_kernel(
    const float* __restrict__ x, const float* __restrict__ gamma,
    const float* __restrict__ beta,
    __nv_bfloat16* __restrict__ out_hi, __nv_bfloat16* __restrict__ out_lo)
{
    int row = blockIdx.x;
    int tid = threadIdx.x;
    const float4* xr = (const float4*)(x + (size_t)row * DMODEL);
    float4 v = xr[tid];

    __shared__ float red[256];
    red[tid] = v.x + v.y + v.z + v.w; __syncthreads();
    #pragma unroll
    for (int off = 128; off > 0; off >>= 1) {
        if (tid < off) red[tid] += red[tid + off];
        __syncthreads();
    }
    float mu = red[0] * (1.0f / DMODEL);
    __syncthreads();

    float dx0 = v.x - mu, dx1 = v.y - mu, dx2 = v.z - mu, dx3 = v.w - mu;
    red[tid] = dx0*dx0 + dx1*dx1 + dx2*dx2 + dx3*dx3; __syncthreads();
    #pragma unroll
    for (int off = 128; off > 0; off >>= 1) {
        if (tid < off) red[tid] += red[tid + off];
        __syncthreads();
    }
    float rs = rsqrtf(red[0] * (1.0f / DMODEL) + 1e-5f);

    float4 g4 = ((const float4*)gamma)[tid];
    float4 b4 = ((const float4*)beta)[tid];
    float o0 = dx0 * rs * g4.x + b4.x;
    float o1 = dx1 * rs * g4.y + b4.y;
    float o2 = dx2 * rs * g4.z + b4.z;
    float o3 = dx3 * rs * g4.w + b4.w;

    __nv_bfloat16 h0,h1,h2,h3, l0,l1,l2,l3;
    split_bf16(o0,h0,l0); split_bf16(o1,h1,l1);
    split_bf16(o2,h2,l2); split_bf16(o3,h3,l3);
    size_t o = (size_t)row * DMODEL + tid * 4;
    *(__nv_bfloat162*)&out_hi[o]   = __halves2bfloat162(h0, h1);
    *(__nv_bfloat162*)&out_hi[o+2] = __halves2bfloat162(h2, h3);
    *(__nv_bfloat162*)&out_lo[o]   = __halves2bfloat162(l0, l1);
    *(__nv_bfloat162*)&out_lo[o+2] = __halves2bfloat162(l2, l3);
}

// ---------------------------------------------------------------------------
// bf16x3 MMA GEMM:  C[M,N] = (Ah+Al)[M,K] @ (Bh+Bl)^T[N,K]  + bias (+R|gelu)
// CTA 128x128xBK16, 8 warps (2x4), warp tile 64x32, m16n8k16 mma.
// EPI: 0 bias->C(f32) | 1 bias+R->C(f32) | 2 bias+gelu->Chi/Clo(bf16)
// ---------------------------------------------------------------------------
template<int EPI>
__global__ __launch_bounds__(256) void mma_gemm(
    const __nv_bfloat16* __restrict__ Ah, const __nv_bfloat16* __restrict__ Al,
    const __nv_bfloat16* __restrict__ Bh, const __nv_bfloat16* __restrict__ Bl,
    const float* __restrict__ bias, const float* __restrict__ R,
    float* __restrict__ C, __nv_bfloat16* __restrict__ Chi,
    __nv_bfloat16* __restrict__ Clo, int M, int N, int K)
{
    __shared__ __align__(16) __nv_bfloat16 smem[2][4][128 * LDS_K];

    const int tid = threadIdx.x;
    const int bm = blockIdx.y * 128;
    const int bn = blockIdx.x * 128;

    // cp.async assignments: thread -> (row, 16B half-row) per matrix
    const int lrow  = tid >> 1;
    const int lhalf = tid & 1;
    const __nv_bfloat16* src0 = Ah + (size_t)(bm + lrow) * K + lhalf * 8;
    const __nv_bfloat16* src1 = Al + (size_t)(bm + lrow) * K + lhalf * 8;
    const __nv_bfloat16* src2 = Bh + (size_t)(bn + lrow) * K + lhalf * 8;
    const __nv_bfloat16* src3 = Bl + (size_t)(bn + lrow) * K + lhalf * 8;
    const int sdst = lrow * LDS_K + lhalf * 8;

    const int warp  = tid >> 5;
    const int lane  = tid & 31;
    const int warpm = warp >> 2;   // 0..1
    const int warpn = warp & 3;    // 0..3
    const int g = lane >> 2;       // 0..7
    const int c = lane & 3;        // 0..3

    float acc[4][4][4];
    #pragma unroll
    for (int i = 0; i < 4; i++)
        #pragma unroll
        for (int j = 0; j < 4; j++)
            #pragma unroll
            for (int r = 0; r < 4; r++) acc[i][j][r] = 0.0f;

    const int nk = K >> 4;

    // prologue: stage 0
    cp16(&smem[0][0][sdst], src0);
    cp16(&smem[0][1][sdst], src1);
    cp16(&smem[0][2][sdst], src2);
    cp16(&smem[0][3][sdst], src3);
    asm volatile("cp.async.commit_group;\n" ::);

    for (int t = 0; t < nk; t++) {
        asm volatile("cp.async.wait_group 0;\n" ::);
        __syncthreads();
        if (t + 1 < nk) {
            int ko = (t + 1) << 4;
            int s = (t + 1) & 1;
            cp16(&smem[s][0][sdst], src0 + ko);
            cp16(&smem[s][1][sdst], src1 + ko);
            cp16(&smem[s][2][sdst], src2 + ko);
            cp16(&smem[s][3][sdst], src3 + ko);
            asm volatile("cp.async.commit_group;\n" ::);
        }

        const __nv_bfloat16* sAh = smem[t & 1][0];
        const __nv_bfloat16* sAl = smem[t & 1][1];
        const __nv_bfloat16* sBh = smem[t & 1][2];
        const __nv_bfloat16* sBl = smem[t & 1][3];

        unsigned ah[4][4], al[4][4], bh[4][2], bl[4][2];
        const int abase = (warpm * 64 + g) * LDS_K + c * 2;
        const int bbase = (warpn * 32 + g) * LDS_K + c * 2;

        #pragma unroll
        for (int mi = 0; mi < 4; mi++) {
            int o = abase + mi * 16 * LDS_K;
            ah[mi][0] = *(const unsigned*)(sAh + o);
            ah[mi][1] = *(const unsigned*)(sAh + o + 8 * LDS_K);
            ah[mi][2] = *(const unsigned*)(sAh + o + 8);
            ah[mi][3] = *(const unsigned*)(sAh + o + 8 * LDS_K + 8);
        }
        #pragma unroll
        for (int ni = 0; ni < 4; ni++) {
            int o = bbase + ni * 8 * LDS_K;
            bh[ni][0] = *(const unsigned*)(sBh + o);
            bh[ni][1] = *(const unsigned*)(sBh + o + 8);
        }
        // hi*hi
        #pragma unroll
        for (int mi = 0; mi < 4; mi++)
            #pragma unroll
            for (int ni = 0; ni < 4; ni++)
                mma_bf16(acc[mi][ni], ah[mi], bh[ni]);
        // lo*hi
        #pragma unroll
        for (int mi = 0; mi < 4; mi++) {
            int o = abase + mi * 16 * LDS_K;
            al[mi][0] = *(const unsigned*)(sAl + o);
            al[mi][1] = *(const unsigned*)(sAl + o + 8 * LDS_K);
            al[mi][2] = *(const unsigned*)(sAl + o + 8);
            al[mi][3] = *(const unsigned*)(sAl + o + 8 * LDS_K + 8);
        }
        #pragma unroll
        for (int mi = 0; mi < 4; mi++)
            #pragma unroll
            for (int ni = 0; ni < 4; ni++)
                mma_bf16(acc[mi][ni], al[mi], bh[ni]);
        // hi*lo
        #pragma unroll
        for (int ni = 0; ni < 4; ni++) {
            int o = bbase + ni * 8 * LDS_K;
            bl[ni][0] = *(const unsigned*)(sBl + o);
            bl[ni][1] = *(const unsigned*)(sBl + o + 8);
        }
        #pragma unroll
        for (int mi = 0; mi < 4; mi++)
            #pragma unroll
            for (int ni = 0; ni < 4; ni++)
                mma_bf16(acc[mi][ni], ah[mi], bl[ni]);
    }

    // epilogue
    #pragma unroll
    for (int mi = 0; mi < 4; mi++) {
        int r0 = bm + warpm * 64 + mi * 16 + g;
        #pragma unroll
        for (int ni = 0; ni < 4; ni++) {
            int col = bn + warpn * 32 + ni * 8 + c * 2;
            float2 bia = *(const float2*)&bias[col];
            float v0 = acc[mi][ni][0] + bia.x;
            float v1 = acc[mi][ni][1] + bia.y;
            float v2 = acc[mi][ni][2] + bia.x;
            float v3 = acc[mi][ni][3] + bia.y;
            size_t o0 = (size_t)r0 * N + col;
            size_t o1 = (size_t)(r0 + 8) * N + col;
            if (EPI == 1) {
                float2 ra = *(const float2*)&R[o0];
                float2 rb = *(const float2*)&R[o1];
                v0 += ra.x; v1 += ra.y; v2 += rb.x; v3 += rb.y;
            }
            if (EPI == 2) {
                v0 = gelu_exact(v0); v1 = gelu_exact(v1);
                v2 = gelu_exact(v2); v3 = gelu_exact(v3);
                __nv_bfloat16 h0,h1,h2,h3, l0,l1,l2,l3;
                split_bf16(v0,h0,l0); split_bf16(v1,h1,l1);
                split_bf16(v2,h2,l2); split_bf16(v3,h3,l3);
                *(__nv_bfloat162*)&Chi[o0] = __halves2bfloat162(h0, h1);
                *(__nv_bfloat162*)&Chi[o1] = __halves2bfloat162(h2, h3);
                *(__nv_bfloat162*)&Clo[o0] = __halves2bfloat162(l0, l1);
                *(__nv_bfloat162*)&Clo[o1] = __halves2bfloat162(l2, l3);
            } else {
                *(float2*)&C[o0] = make_float2(v0, v1);
                *(float2*)&C[o1] = make_float2(v2, v3);
            }
        }
    }
}

// ---------------------------------------------------------------------------
// Flash-style attention (fp32). Writes ctx as bf16 hi/lo for the Wo GEMM.
// ---------------------------------------------------------------------------
__global__ __launch_bounds__(64) void attn_kernel(
    const float* __restrict__ Q, const float* __restrict__ K,
    const float* __restrict__ V, const int* __restrict__ mask,
    __nv_bfloat16* __restrict__ Ohi, __nv_bfloat16* __restrict__ Olo)
{
    int b  = blockIdx.z;
    int h  = blockIdx.y;
    int qt = blockIdx.x;
    int tid = threadIdx.x;            // 0..63
    int qi = qt * 64 + tid;

    const float* qptr = Q + ((size_t)(b * SEQ + qi) * DMODEL) + h * DK;
    float qreg[DK];
    #pragma unroll
    for (int d4 = 0; d4 < 16; d4++) {
        float4 t = ((const float4*)qptr)[d4];
        qreg[d4*4+0] = t.x; qreg[d4*4+1] = t.y;
        qreg[d4*4+2] = t.z; qreg[d4*4+3] = t.w;
    }

    __shared__ float Ks[64][DK];
    __shared__ float Vs[64][DK];
    __shared__ int   ms[64];

    float m = -1e30f, l = 0.0f;
    float o[DK];
    #pragma unroll
    for (int d = 0; d < DK; d++) o[d] = 0.0f;

    for (int kt = 0; kt < SEQ / 64; kt++) {
        int kj = kt * 64 + tid;
        const float* kptr = K + ((size_t)(b * SEQ + kj) * DMODEL) + h * DK;
        const float* vptr = V + ((size_t)(b * SEQ + kj) * DMODEL) + h * DK;
        __syncthreads();
        #pragma unroll
        for (int d4 = 0; d4 < 16; d4++) {
            ((float4*)Ks[tid])[d4] = ((const float4*)kptr)[d4];
            ((float4*)Vs[tid])[d4] = ((const float4*)vptr)[d4];
        }
        ms[tid] = mask[b * SEQ + kj];
        __syncthreads();

        #pragma unroll 1
        for (int j0 = 0; j0 < 64; j0 += 16) {
            float sc[16];
            #pragma unroll
            for (int jj = 0; jj < 16; jj++) {
                const float4* kr = (const float4*)Ks[j0 + jj];
                float s0 = 0.f, s1 = 0.f, s2 = 0.f, s3 = 0.f;
                #pragma unroll
                for (int d4 = 0; d4 < 16; d4++) {
                    float4 kv = kr[d4];
                    s0 = fmaf(qreg[d4*4+0], kv.x, s0);
                    s1 = fmaf(qreg[d4*4+1], kv.y, s1);
                    s2 = fmaf(qreg[d4*4+2], kv.z, s2);
                    s3 = fmaf(qreg[d4*4+3], kv.w, s3);
                }
                float s = ((s0 + s1) + (s2 + s3)) * 0.125f;  // 1/sqrt(64)
                sc[jj] = (ms[j0 + jj] != 0) ? s : -1e30f;
            }
            float tmax = m;
            #pragma unroll
            for (int jj = 0; jj < 16; jj++) tmax = fmaxf(tmax, sc[jj]);
            float scale = __expf(m - tmax);
            m = tmax;
            l *= scale;
            #pragma unroll
            for (int d = 0; d < DK; d++) o[d] *= scale;
            #pragma unroll
            for (int jj = 0; jj < 16; jj++) {
                float p = __expf(sc[jj] - m);
                l += p;
                const float4* vr = (const float4*)Vs[j0 + jj];
                #pragma unroll
                for (int d4 = 0; d4 < 16; d4++) {
                    float4 vv = vr[d4];
                    o[d4*4+0] = fmaf(p, vv.x, o[d4*4+0]);
                    o[d4*4+1] = fmaf(p, vv.y, o[d4*4+1]);
                    o[d4*4+2] = fmaf(p, vv.z, o[d4*4+2]);
                    o[d4*4+3] = fmaf(p, vv.w, o[d4*4+3]);
                }
            }
        }
    }

    float inv = 1.0f / l;
    size_t obase = ((size_t)(b * SEQ + qi) * DMODEL) + h * DK;
    #pragma unroll
    for (int d2 = 0; d2 < 32; d2++) {
        float v0 = o[d2*2+0] * inv;
        float v1 = o[d2*2+1] * inv;
        __nv_bfloat16 h0,h1, l0,l1;
        split_bf16(v0,h0,l0); split_bf16(v1,h1,l1);
        *(__nv_bfloat162*)&Ohi[obase + d2*2] = __halves2bfloat162(h0, h1);
        *(__nv_bfloat162*)&Olo[obase + d2*2] = __halves2bfloat162(l0, l1);
    }
}

// ---------------------------------------------------------------------------
// Host launch
// ---------------------------------------------------------------------------
extern "C" void kernel_launch(void* const* d_in, const int* in_sizes, int n_in,
                              void* d_out, int out_size)
{
    const float* x     = (const float*)d_in[0];
    const int*   mask  = (const int*)  d_in[1];
    const float* Wq    = (const float*)d_in[2];
    const float* bq    = (const float*)d_in[3];
    const float* Wk    = (const float*)d_in[4];
    const float* bk    = (const float*)d_in[5];
    const float* Wv    = (const float*)d_in[6];
    const float* bv    = (const float*)d_in[7];
    const float* Wo    = (const float*)d_in[8];
    const float* bo    = (const float*)d_in[9];
    const float* W1    = (const float*)d_in[10];
    const float* b1    = (const float*)d_in[11];
    const float* W2    = (const float*)d_in[12];
    const float* b2    = (const float*)d_in[13];
    const float* ln1_g = (const float*)d_in[14];
    const float* ln1_b = (const float*)d_in[15];
    const float* ln2_g = (const float*)d_in[16];
    const float* ln2_b = (const float*)d_in[17];
    float* out = (float*)d_out;

    float *qb, *kb, *vb, *x1;
    __nv_bfloat16 *hh, *hl, *ctxh, *ctxl, *h2h, *h2l, *ffnh, *ffnl;
    __nv_bfloat16 *wqh,*wql,*wkh,*wkl,*wvh,*wvl,*woh,*wol,*w1h,*w1l,*w2h,*w2l;
    cudaGetSymbolAddress((void**)&qb,  g_q);
    cudaGetSymbolAddress((void**)&kb,  g_k);
    cudaGetSymbolAddress((void**)&vb,  g_v);
    cudaGetSymbolAddress((void**)&x1,  g_x1);
    cudaGetSymbolAddress((void**)&hh,  g_hh);
    cudaGetSymbolAddress((void**)&hl,  g_hl);
    cudaGetSymbolAddress((void**)&ctxh, g_ctxh);
    cudaGetSymbolAddress((void**)&ctxl, g_ctxl);
    cudaGetSymbolAddress((void**)&h2h, g_h2h);
    cudaGetSymbolAddress((void**)&h2l, g_h2l);
    cudaGetSymbolAddress((void**)&ffnh, g_ffnh);
    cudaGetSymbolAddress((void**)&ffnl, g_ffnl);
    cudaGetSymbolAddress((void**)&wqh, g_wqh); cudaGetSymbolAddress((void**)&wql, g_wql);
    cudaGetSymbolAddress((void**)&wkh, g_wkh); cudaGetSymbolAddress((void**)&wkl, g_wkl);
    cudaGetSymbolAddress((void**)&wvh, g_wvh); cudaGetSymbolAddress((void**)&wvl, g_wvl);
    cudaGetSymbolAddress((void**)&woh, g_woh); cudaGetSymbolAddress((void**)&wol, g_wol);
    cudaGetSymbolAddress((void**)&w1h, g_w1h); cudaGetSymbolAddress((void**)&w1l, g_w1l);
    cudaGetSymbolAddress((void**)&w2h, g_w2h); cudaGetSymbolAddress((void**)&w2l, g_w2l);

    // 0) weight split+transpose
    dim3 gW(DMODEL/32, DMODEL/32);
    wsplit_kernel<<<gW, 256>>>(Wq, wqh, wql, DMODEL, DMODEL);
    wsplit_kernel<<<gW, 256>>>(Wk, wkh, wkl, DMODEL, DMODEL);
    wsplit_kernel<<<gW, 256>>>(Wv, wvh, wvl, DMODEL, DMODEL);
    wsplit_kernel<<<gW, 256>>>(Wo, woh, wol, DMODEL, DMODEL);
    dim3 gW1(DFF/32, DMODEL/32);
    wsplit_kernel<<<gW1, 256>>>(W1, w1h, w1l, DMODEL, DFF);
    dim3 gW2(DMODEL/32, DFF/32);
    wsplit_kernel<<<gW2, 256>>>(W2, w2h, w2l, DFF, DMODEL);

    // 1) LN1 -> bf16 split
    ln_kernel<<<MROWS, 256>>>(x, ln1_g, ln1_b, hh, hl);

    // 2) QKV projections (fp32 out)
    dim3 gP(DMODEL/128, MROWS/128);   // (8, 64)
    mma_gemm<0><<<gP, 256>>>(hh, hl, wqh, wql, bq, nullptr, qb, nullptr, nullptr, MROWS, DMODEL, DMODEL);
    mma_gemm<0><<<gP, 256>>>(hh, hl, wkh, wkl, bk, nullptr, kb, nullptr, nullptr, MROWS, DMODEL, DMODEL);
    mma_gemm<0><<<gP, 256>>>(hh, hl, wvh, wvl, bv, nullptr, vb, nullptr, nullptr, MROWS, DMODEL, DMODEL);

    // 3) attention -> ctx bf16 split
    dim3 gA(SEQ/64, NHEADS, BATCH);
    attn_kernel<<<gA, 64>>>(qb, kb, vb, mask, ctxh, ctxl);

    // 4) output projection + residual -> x1 (fp32)
    mma_gemm<1><<<gP, 256>>>(ctxh, ctxl, woh, wol, bo, x, x1, nullptr, nullptr, MROWS, DMODEL, DMODEL);

    // 5) LN2 -> bf16 split
    ln_kernel<<<MROWS, 256>>>(x1, ln2_g, ln2_b, h2h, h2l);

    // 6) FFN up + GELU -> ffn bf16 split
    dim3 gF1(DFF/128, MROWS/128);     // (32, 64)
    mma_gemm<2><<<gF1, 256>>>(h2h, h2l, w1h, w1l, b1, nullptr, nullptr, ffnh, ffnl, MROWS, DFF, DMODEL);

    // 7) FFN down + residual -> out (fp32)
    dim3 gF2(DMODEL/128, MROWS/128);  // (8, 64)
    mma_gemm<1><<<gF2, 256>>>(ffnh, ffnl, w2h, w2l, b2, x1, out, nullptr, nullptr, MROWS, DMODEL, DFF);
}

// round 4
// speedup vs baseline: 2.9653x; 1.9740x over previous
#include <cuda_runtime.h>
#include <cuda_bf16.h>
#include <math.h>

// ---------------------------------------------------------------------------
// TransformerEncoderBlock: B=4, S=2048, D=1024, H=16, Dk=64, Dff=4096, fp32.
// Round 4: GEMMs on mma.sync bf16 hi/lo split (R3) + tensor-core flash
// attention (hi/lo split both stages, ldmatrix, cp.async) + FFMA-only exp.
// ---------------------------------------------------------------------------

#define BATCH   4
#define SEQ     2048
#define DMODEL  1024
#define NHEADS  16
#define DK      64
#define DFF     4096
#define MROWS   (BATCH * SEQ)   // 8192

#define LDS_K   24              // GEMM smem pad

// ---------------- scratch (__device__ globals; no allocs allowed) ----------
__device__ float g_x1[MROWS * DMODEL];

__device__ __align__(16) __nv_bfloat16 g_hh  [MROWS * DMODEL];
__device__ __align__(16) __nv_bfloat16 g_hl  [MROWS * DMODEL];
__device__ __align__(16) __nv_bfloat16 g_qh  [MROWS * DMODEL];
__device__ __align__(16) __nv_bfloat16 g_ql  [MROWS * DMODEL];
__device__ __align__(16) __nv_bfloat16 g_kh  [MROWS * DMODEL];
__device__ __align__(16) __nv_bfloat16 g_kl  [MROWS * DMODEL];
__device__ __align__(16) __nv_bfloat16 g_vh  [MROWS * DMODEL];
__device__ __align__(16) __nv_bfloat16 g_vl  [MROWS * DMODEL];
__device__ __align__(16) __nv_bfloat16 g_ctxh[MROWS * DMODEL];
__device__ __align__(16) __nv_bfloat16 g_ctxl[MROWS * DMODEL];
__device__ __align__(16) __nv_bfloat16 g_h2h [MROWS * DMODEL];
__device__ __align__(16) __nv_bfloat16 g_h2l [MROWS * DMODEL];
__device__ __align__(16) __nv_bfloat16 g_ffnh[MROWS * DFF];
__device__ __align__(16) __nv_bfloat16 g_ffnl[MROWS * DFF];

__device__ __align__(16) __nv_bfloat16 g_wqh[DMODEL*DMODEL], g_wql[DMODEL*DMODEL];
__device__ __align__(16) __nv_bfloat16 g_wkh[DMODEL*DMODEL], g_wkl[DMODEL*DMODEL];
__device__ __align__(16) __nv_bfloat16 g_wvh[DMODEL*DMODEL], g_wvl[DMODEL*DMODEL];
__device__ __align__(16) __nv_bfloat16 g_woh[DMODEL*DMODEL], g_wol[DMODEL*DMODEL];
__device__ __align__(16) __nv_bfloat16 g_w1h[DFF*DMODEL],    g_w1l[DFF*DMODEL];
__device__ __align__(16) __nv_bfloat16 g_w2h[DMODEL*DFF],    g_w2l[DMODEL*DFF];

// ---------------------------------------------------------------------------
__device__ __forceinline__ void split_bf16(float v, __nv_bfloat16& hi, __nv_bfloat16& lo) {
    hi = __float2bfloat16(v);
    lo = __float2bfloat16(v - __bfloat162float(hi));
}

__device__ __forceinline__ float gelu_exact(float x) {
    return 0.5f * x * (1.0f + erff(x * 0.70710678118654752f));
}

__device__ __forceinline__ void cp16(const void* dst_smem, const void* src) {
    unsigned s = (unsigned)__cvta_generic_to_shared(dst_smem);
    asm volatile("cp.async.cg.shared.global [%0], [%1], 16;\n" :: "r"(s), "l"(src));
}

__device__ __forceinline__ void mma_bf16(float* c, const unsigned* a, const unsigned* b) {
    asm volatile(
        "mma.sync.aligned.m16n8k16.row.col.f32.bf16.bf16.f32 "
        "{%0,%1,%2,%3}, {%4,%5,%6,%7}, {%8,%9}, {%0,%1,%2,%3};\n"
        : "+f"(c[0]), "+f"(c[1]), "+f"(c[2]), "+f"(c[3])
        : "r"(a[0]), "r"(a[1]), "r"(a[2]), "r"(a[3]), "r"(b[0]), "r"(b[1]));
}

__device__ __forceinline__ void ldsm4(unsigned& r0, unsigned& r1, unsigned& r2, unsigned& r3, unsigned addr) {
    asm volatile("ldmatrix.sync.aligned.m8n8.x4.shared.b16 {%0,%1,%2,%3}, [%4];"
                 : "=r"(r0), "=r"(r1), "=r"(r2), "=r"(r3) : "r"(addr));
}
__device__ __forceinline__ void ldsm4t(unsigned& r0, unsigned& r1, unsigned& r2, unsigned& r3, unsigned addr) {
    asm volatile("ldmatrix.sync.aligned.m8n8.x4.trans.shared.b16 {%0,%1,%2,%3}, [%4];"
                 : "=r"(r0), "=r"(r1), "=r"(r2), "=r"(r3) : "r"(addr));
}

// FFMA-only e^x for x <= 0 (clamped). rel err ~4e-5.
__device__ __forceinline__ float fexp(float x) {
    x = fmaxf(x, -60.0f);
    float t = x * 1.4426950408889634f;
    float z = t + 12582912.0f;                 // round t to nearest int
    int   e = __float_as_int(z) - 0x4B400000;  // = round(t)
    float f = t - (z - 12582912.0f);           // t - round(t) in [-0.5, 0.5]
    float p = 0.0096181291f;
    p = fmaf(p, f, 0.0555041087f);
    p = fmaf(p, f, 0.2402265070f);
    p = fmaf(p, f, 0.6931471806f);
    p = fmaf(p, f, 1.0f);
    return __int_as_float(__float_as_int(p) + (e << 23));
}

// pack two floats -> bf16x2 hi, and residual lo
__device__ __forceinline__ void pack_hilo(float a, float b, unsigned& hi, unsigned& lo) {
    __nv_bfloat162 h2 = __float22bfloat162_rn(make_float2(a, b));
    float2 hf = __bfloat1622float2(h2);
    __nv_bfloat162 l2 = __float22bfloat162_rn(make_float2(a - hf.x, b - hf.y));
    hi = *(unsigned*)&h2;
    lo = *(unsigned*)&l2;
}

// ---------------------------------------------------------------------------
// Weight split + transpose:  W[K][N] fp32  ->  Th/Tl[N][K] bf16
// ---------------------------------------------------------------------------
__global__ __launch_bounds__(256) void wsplit_kernel(
    const float* __restrict__ W, __nv_bfloat16* __restrict__ Th,
    __nv_bfloat16* __restrict__ Tl, int K, int N)
{
    __shared__ float tile[32][33];
    int n0 = blockIdx.x * 32, k0 = blockIdx.y * 32;
    int tx = threadIdx.x & 31;
    int ty = threadIdx.x >> 5;
    #pragma unroll
    for (int i = 0; i < 32; i += 8)
        tile[ty + i][tx] = W[(size_t)(k0 + ty + i) * N + n0 + tx];
    __syncthreads();
    #pragma unroll
    for (int i = 0; i < 32; i += 8) {
        float v = tile[tx][ty + i];
        __nv_bfloat16 hi, lo; split_bf16(v, hi, lo);
        size_t o = (size_t)(n0 + ty + i) * K + k0 + tx;
        Th[o] = hi; Tl[o] = lo;
    }
}

// ---------------------------------------------------------------------------
// LayerNorm -> bf16 hi/lo outputs.
// ---------------------------------------------------------------------------
__global__ __launch_bounds__(256) void ln_kernel(
    const float* __restrict__ x, const float* __restrict__ gamma,
    const float* __restrict__ beta,
    __nv_bfloat16* __restrict__ out_hi, __nv_bfloat16* __restrict__ out_lo)
{
    int row = blockIdx.x;
    int tid = threadIdx.x;
    const float4* xr = (const float4*)(x + (size_t)row * DMODEL);
    float4 v = xr[tid];

    __shared__ float red[256];
    red[tid] = v.x + v.y + v.z + v.w; __syncthreads();
    #pragma unroll
    for (int off = 128; off > 0; off >>= 1) {
        if (tid < off) red[tid] += red[tid + off];
        __syncthreads();
    }
    float mu = red[0] * (1.0f / DMODEL);
    __syncthreads();

    float dx0 = v.x - mu, dx1 = v.y - mu, dx2 = v.z - mu, dx3 = v.w - mu;
    red[tid] = dx0*dx0 + dx1*dx1 + dx2*dx2 + dx3*dx3; __syncthreads();
    #pragma unroll
    for (int off = 128; off > 0; off >>= 1) {
        if (tid < off) red[tid] += red[tid + off];
        __syncthreads();
    }
    float rs = rsqrtf(red[0] * (1.0f / DMODEL) + 1e-5f);

    float4 g4 = ((const float4*)gamma)[tid];
    float4 b4 = ((const float4*)beta)[tid];
    float o0 = dx0 * rs * g4.x + b4.x;
    float o1 = dx1 * rs * g4.y + b4.y;
    float o2 = dx2 * rs * g4.z + b4.z;
    float o3 = dx3 * rs * g4.w + b4.w;

    unsigned h01, l01, h23, l23;
    pack_hilo(o0, o1, h01, l01);
    pack_hilo(o2, o3, h23, l23);
    size_t o = (size_t)row * DMODEL + tid * 4;
    *(unsigned*)&out_hi[o]   = h01; *(unsigned*)&out_hi[o+2] = h23;
    *(unsigned*)&out_lo[o]   = l01; *(unsigned*)&out_lo[o+2] = l23;
}

// ---------------------------------------------------------------------------
// bf16x3 MMA GEMM (as R3).  EPI: 0 bias->f32 | 1 bias+R->f32
//                                2 bias+gelu->bf16 hi/lo | 3 bias->bf16 hi/lo
// ---------------------------------------------------------------------------
template<int EPI>
__global__ __launch_bounds__(256) void mma_gemm(
    const __nv_bfloat16* __restrict__ Ah, const __nv_bfloat16* __restrict__ Al,
    const __nv_bfloat16* __restrict__ Bh, const __nv_bfloat16* __restrict__ Bl,
    const float* __restrict__ bias, const float* __restrict__ R,
    float* __restrict__ C, __nv_bfloat16* __restrict__ Chi,
    __nv_bfloat16* __restrict__ Clo, int M, int N, int K)
{
    __shared__ __align__(16) __nv_bfloat16 smem[2][4][128 * LDS_K];

    const int tid = threadIdx.x;
    const int bm = blockIdx.y * 128;
    const int bn = blockIdx.x * 128;

    const int lrow  = tid >> 1;
    const int lhalf = tid & 1;
    const __nv_bfloat16* src0 = Ah + (size_t)(bm + lrow) * K + lhalf * 8;
    const __nv_bfloat16* src1 = Al + (size_t)(bm + lrow) * K + lhalf * 8;
    const __nv_bfloat16* src2 = Bh + (size_t)(bn + lrow) * K + lhalf * 8;
    const __nv_bfloat16* src3 = Bl + (size_t)(bn + lrow) * K + lhalf * 8;
    const int sdst = lrow * LDS_K + lhalf * 8;

    const int warp  = tid >> 5;
    const int lane  = tid & 31;
    const int warpm = warp >> 2;
    const int warpn = warp & 3;
    const int g = lane >> 2;
    const int c = lane & 3;

    float acc[4][4][4];
    #pragma unroll
    for (int i = 0; i < 4; i++)
        #pragma unroll
        for (int j = 0; j < 4; j++)
            #pragma unroll
            for (int r = 0; r < 4; r++) acc[i][j][r] = 0.0f;

    const int nk = K >> 4;

    cp16(&smem[0][0][sdst], src0);
    cp16(&smem[0][1][sdst], src1);
    cp16(&smem[0][2][sdst], src2);
    cp16(&smem[0][3][sdst], src3);
    asm volatile("cp.async.commit_group;\n" ::);

    for (int t = 0; t < nk; t++) {
        asm volatile("cp.async.wait_group 0;\n" ::);
        __syncthreads();
        if (t + 1 < nk) {
            int ko = (t + 1) << 4;
            int s = (t + 1) & 1;
            cp16(&smem[s][0][sdst], src0 + ko);
            cp16(&smem[s][1][sdst], src1 + ko);
            cp16(&smem[s][2][sdst], src2 + ko);
            cp16(&smem[s][3][sdst], src3 + ko);
            asm volatile("cp.async.commit_group;\n" ::);
        }

        const __nv_bfloat16* sAh = smem[t & 1][0];
        const __nv_bfloat16* sAl = smem[t & 1][1];
        const __nv_bfloat16* sBh = smem[t & 1][2];
        const __nv_bfloat16* sBl = smem[t & 1][3];

        unsigned ah[4][4], al[4][4], bh[4][2], bl[4][2];
        const int abase = (warpm * 64 + g) * LDS_K + c * 2;
        const int bbase = (warpn * 32 + g) * LDS_K + c * 2;

        #pragma unroll
        for (int mi = 0; mi < 4; mi++) {
            int o = abase + mi * 16 * LDS_K;
            ah[mi][0] = *(const unsigned*)(sAh + o);
            ah[mi][1] = *(const unsigned*)(sAh + o + 8 * LDS_K);
            ah[mi][2] = *(const unsigned*)(sAh + o + 8);
            ah[mi][3] = *(const unsigned*)(sAh + o + 8 * LDS_K + 8);
        }
        #pragma unroll
        for (int ni = 0; ni < 4; ni++) {
            int o = bbase + ni * 8 * LDS_K;
            bh[ni][0] = *(const unsigned*)(sBh + o);
            bh[ni][1] = *(const unsigned*)(sBh + o + 8);
        }
        #pragma unroll
        for (int mi = 0; mi < 4; mi++)
            #pragma unroll
            for (int ni = 0; ni < 4; ni++)
                mma_bf16(acc[mi][ni], ah[mi], bh[ni]);
        #pragma unroll
        for (int mi = 0; mi < 4; mi++) {
            int o = abase + mi * 16 * LDS_K;
            al[mi][0] = *(const unsigned*)(sAl + o);
            al[mi][1] = *(const unsigned*)(sAl + o + 8 * LDS_K);
            al[mi][2] = *(const unsigned*)(sAl + o + 8);
            al[mi][3] = *(const unsigned*)(sAl + o + 8 * LDS_K + 8);
        }
        #pragma unroll
        for (int mi = 0; mi < 4; mi++)
            #pragma unroll
            for (int ni = 0; ni < 4; ni++)
                mma_bf16(acc[mi][ni], al[mi], bh[ni]);
        #pragma unroll
        for (int ni = 0; ni < 4; ni++) {
            int o = bbase + ni * 8 * LDS_K;
            bl[ni][0] = *(const unsigned*)(sBl + o);
            bl[ni][1] = *(const unsigned*)(sBl + o + 8);
        }
        #pragma unroll
        for (int mi = 0; mi < 4; mi++)
            #pragma unroll
            for (int ni = 0; ni < 4; ni++)
                mma_bf16(acc[mi][ni], ah[mi], bl[ni]);
    }

    #pragma unroll
    for (int mi = 0; mi < 4; mi++) {
        int r0 = bm + warpm * 64 + mi * 16 + g;
        #pragma unroll
        for (int ni = 0; ni < 4; ni++) {
            int col = bn + warpn * 32 + ni * 8 + c * 2;
            float2 bia = *(const float2*)&bias[col];
            float v0 = acc[mi][ni][0] + bia.x;
            float v1 = acc[mi][ni][1] + bia.y;
            float v2 = acc[mi][ni][2] + bia.x;
            float v3 = acc[mi][ni][3] + bia.y;
            size_t o0 = (size_t)r0 * N + col;
            size_t o1 = (size_t)(r0 + 8) * N + col;
            if (EPI == 1) {
                float2 ra = *(const float2*)&R[o0];
                float2 rb = *(const float2*)&R[o1];
                v0 += ra.x; v1 += ra.y; v2 += rb.x; v3 += rb.y;
            }
            if (EPI == 2) {
                v0 = gelu_exact(v0); v1 = gelu_exact(v1);
                v2 = gelu_exact(v2); v3 = gelu_exact(v3);
            }
            if (EPI == 2 || EPI == 3) {
                unsigned h01, l01, h23, l23;
                pack_hilo(v0, v1, h01, l01);
                pack_hilo(v2, v3, h23, l23);
                *(unsigned*)&Chi[o0] = h01; *(unsigned*)&Chi[o1] = h23;
                *(unsigned*)&Clo[o0] = l01; *(unsigned*)&Clo[o1] = l23;
            } else {
                *(float2*)&C[o0] = make_float2(v0, v1);
                *(float2*)&C[o1] = make_float2(v2, v3);
            }
        }
    }
}

// ---------------------------------------------------------------------------
// Tensor-core flash attention.
// CTA: 128 threads (4 warps), 64 queries for one (b,h). 64-key tiles.
// smem tiles 64x64 bf16, 128B rows, XOR-swizzled 16B chunks.
// Dynamic smem layout (bytes):
//   Qh:0  Ql:8192  K/V stages: Kh[2],Kl[2],Vh[2],Vl[2] at 16384+...  fmask[2][64]
// ---------------------------------------------------------------------------
#define ATT_QH   0
#define ATT_QL   8192
#define ATT_KH   16384          // + s*8192*4 per stage block below
#define ATT_TILE 8192
// stage s block: KH: 16384 + s*32768, KL: +8192, VH: +16384, VL: +24576
#define ATT_FM   (16384 + 2*32768)   // 81920, float[2][64]
#define ATT_SMEM (ATT_FM + 2*64*4)   // 82432

__device__ __forceinline__ unsigned swz(unsigned base, int row, int cc) {
    return base + (unsigned)((row << 7) + (((cc ^ row) & 7) << 4) + ((cc >> 3) << 7));
}
// (cc < 8 always here; the >>3 term is dead but keeps the formula total)

__global__ __launch_bounds__(128) void attn_mma(
    const __nv_bfloat16* __restrict__ Qh, const __nv_bfloat16* __restrict__ Ql,
    const __nv_bfloat16* __restrict__ Kh, const __nv_bfloat16* __restrict__ Kl,
    const __nv_bfloat16* __restrict__ Vh, const __nv_bfloat16* __restrict__ Vl,
    const int* __restrict__ mask,
    __nv_bfloat16* __restrict__ Ohi, __nv_bfloat16* __restrict__ Olo)
{
    extern __shared__ __align__(16) char sm[];
    const unsigned smb = (unsigned)__cvta_generic_to_shared(sm);
    float* fmask = (float*)(sm + ATT_FM);

    const int b  = blockIdx.z;
    const int h  = blockIdx.y;
    const int qt = blockIdx.x;
    const int tid  = threadIdx.x;
    const int warp = tid >> 5;
    const int lane = tid & 31;
    const int li  = lane & 7;
    const int grp = lane >> 3;
    const int g = lane >> 2;
    const int c = lane & 3;

    const int qrow0 = qt * 64;               // global query base
    const size_t rowQ = (size_t)(b * SEQ + qrow0);

    // ---- prologue: stage Q + tile 0 ----
    {
        // Q hi/lo: 64 rows x 8 chunks each
        #pragma unroll
        for (int i = 0; i < 4; i++) {
            int idx = tid + i * 128;
            int row = idx >> 3, cc = idx & 7;
            const __nv_bfloat16* sq = Qh + (rowQ + row) * DMODEL + h * DK + cc * 8;
            const __nv_bfloat16* sq2 = Ql + (rowQ + row) * DMODEL + h * DK + cc * 8;
            cp16(sm + swz(ATT_QH, row, cc), sq);
            cp16(sm + swz(ATT_QL, row, cc), sq2);
        }
        // K/V tile 0
        #pragma unroll
        for (int i = 0; i < 4; i++) {
            int idx = tid + i * 128;
            int row = idx >> 3, cc = idx & 7;
            size_t gr = (size_t)(b * SEQ + row) * DMODEL + h * DK + cc * 8;
            cp16(sm + swz(ATT_KH + 0*32768, row, cc), Kh + gr);
            cp16(sm + swz(ATT_KH + 0*32768 + ATT_TILE, row, cc), Kl + gr);
            cp16(sm + swz(ATT_KH + 0*32768 + 2*ATT_TILE, row, cc), Vh + gr);
            cp16(sm + swz(ATT_KH + 0*32768 + 3*ATT_TILE, row, cc), Vl + gr);
        }
        if (tid < 64) fmask[tid] = (mask[b * SEQ + tid] != 0) ? 0.0f : -1e30f;
        asm volatile("cp.async.commit_group;\n" ::);
    }

    // per-thread state
    float oacc[8][4];
    #pragma unroll
    for (int nt = 0; nt < 8; nt++)
        #pragma unroll
        for (int r = 0; r < 4; r++) oacc[nt][r] = 0.0f;
    float m0 = -1e30f, m1 = -1e30f, l0 = 0.0f, l1 = 0.0f;
    unsigned qfh[4][4], qfl[4][4];

    const int NT = SEQ / 64;   // 32 key tiles
    for (int kt = 0; kt < NT; kt++) {
        asm volatile("cp.async.wait_group 0;\n" ::);
        __syncthreads();

        if (kt == 0) {
            // Q fragments (held for whole loop): A-layout ldmatrix
            int qrow = warp * 16 + ((grp & 1) << 3) + li;
            #pragma unroll
            for (int q = 0; q < 4; q++) {
                int cc = 2 * q + (grp >> 1);
                ldsm4(qfh[q][0], qfh[q][1], qfh[q][2], qfh[q][3], smb + swz(ATT_QH, qrow, cc));
                ldsm4(qfl[q][0], qfl[q][1], qfl[q][2], qfl[q][3], smb + swz(ATT_QL, qrow, cc));
            }
        }

        // prefetch next tile
        if (kt + 1 < NT) {
            int s = (kt + 1) & 1;
            int kb = (kt + 1) * 64;
            #pragma unroll
            for (int i = 0; i < 4; i++) {
                int idx = tid + i * 128;
                int row = idx >> 3, cc = idx & 7;
                size_t gr = (size_t)(b * SEQ + kb + row) * DMODEL + h * DK + cc * 8;
                cp16(sm + swz(ATT_KH + s*32768, row, cc), Kh + gr);
                cp16(sm + swz(ATT_KH + s*32768 + ATT_TILE, row, cc), Kl + gr);
                cp16(sm + swz(ATT_KH + s*32768 + 2*ATT_TILE, row, cc), Vh + gr);
                cp16(sm + swz(ATT_KH + s*32768 + 3*ATT_TILE, row, cc), Vl + gr);
            }
            if (tid < 64) fmask[s * 64 + tid] = (mask[b * SEQ + kb + tid] != 0) ? 0.0f : -1e30f;
            asm volatile("cp.async.commit_group;\n" ::);
        }

        const int s = kt & 1;
        const unsigned KHb = ATT_KH + s*32768;
        const unsigned KLb = KHb + ATT_TILE;
        const unsigned VHb = KHb + 2*ATT_TILE;
        const unsigned VLb = KHb + 3*ATT_TILE;
        const float* fm = fmask + s * 64;

        // ---- scores S[8 ntiles][4] ----
        float sacc[8][4];
        #pragma unroll
        for (int nt = 0; nt < 8; nt++)
            #pragma unroll
            for (int r = 0; r < 4; r++) sacc[nt][r] = 0.0f;

        {
            const int krow = ((grp >> 1) << 3) + li;   // + 16p
            const int kccb = grp & 1;                  // + 2q
            #pragma unroll
            for (int q = 0; q < 4; q++) {
                unsigned kb2[8][2];
                #pragma unroll
                for (int p = 0; p < 4; p++)
                    ldsm4(kb2[2*p][0], kb2[2*p][1], kb2[2*p+1][0], kb2[2*p+1][1],
                          smb + swz(KHb, 16*p + krow, 2*q + kccb));
                #pragma unroll
                for (int nt = 0; nt < 8; nt++) mma_bf16(sacc[nt], qfh[q], kb2[nt]);
                #pragma unroll
                for (int nt = 0; nt < 8; nt++) mma_bf16(sacc[nt], qfl[q], kb2[nt]);
                #pragma unroll
                for (int p = 0; p < 4; p++)
                    ldsm4(kb2[2*p][0], kb2[2*p][1], kb2[2*p+1][0], kb2[2*p+1][1],
                          smb + swz(KLb, 16*p + krow, 2*q + kccb));
                #pragma unroll
                for (int nt = 0; nt < 8; nt++) mma_bf16(sacc[nt], qfh[q], kb2[nt]);
            }
        }

        // ---- online softmax ----
        float mx0 = -1e30f, mx1 = -1e30f;
        #pragma unroll
        for (int nt = 0; nt < 8; nt++) {
            float f0 = fm[nt*8 + 2*c];
            float f1 = fm[nt*8 + 2*c + 1];
            sacc[nt][0] = fmaf(sacc[nt][0], 0.125f, f0);
            sacc[nt][1] = fmaf(sacc[nt][1], 0.125f, f1);
            sacc[nt][2] = fmaf(sacc[nt][2], 0.125f, f0);
            sacc[nt][3] = fmaf(sacc[nt][3], 0.125f, f1);
            mx0 = fmaxf(mx0, fmaxf(sacc[nt][0], sacc[nt][1]));
            mx1 = fmaxf(mx1, fmaxf(sacc[nt][2], sacc[nt][3]));
        }
        mx0 = fmaxf(mx0, __shfl_xor_sync(0xffffffff, mx0, 1));
        mx0 = fmaxf(mx0, __shfl_xor_sync(0xffffffff, mx0, 2));
        mx1 = fmaxf(mx1, __shfl_xor_sync(0xffffffff, mx1, 1));
        mx1 = fmaxf(mx1, __shfl_xor_sync(0xffffffff, mx1, 2));

        float nm0 = fmaxf(m0, mx0), nm1 = fmaxf(m1, mx1);
        float sc0 = fexp(m0 - nm0), sc1 = fexp(m1 - nm1);
        m0 = nm0; m1 = nm1;
        l0 *= sc0; l1 *= sc1;
        #pragma unroll
        for (int nt = 0; nt < 8; nt++) {
            oacc[nt][0] *= sc0; oacc[nt][1] *= sc0;
            oacc[nt][2] *= sc1; oacc[nt][3] *= sc1;
        }

        float ls0 = 0.0f, ls1 = 0.0f;
        #pragma unroll
        for (int nt = 0; nt < 8; nt++) {
            float p0 = fexp(sacc[nt][0] - nm0);
            float p1 = fexp(sacc[nt][1] - nm0);
            float p2 = fexp(sacc[nt][2] - nm1);
            float p3 = fexp(sacc[nt][3] - nm1);
            sacc[nt][0] = p0; sacc[nt][1] = p1; sacc[nt][2] = p2; sacc[nt][3] = p3;
            ls0 += p0 + p1; ls1 += p2 + p3;
        }
        ls0 += __shfl_xor_sync(0xffffffff, ls0, 1);
        ls0 += __shfl_xor_sync(0xffffffff, ls0, 2);
        ls1 += __shfl_xor_sync(0xffffffff, ls1, 1);
        ls1 += __shfl_xor_sync(0xffffffff, ls1, 2);
        l0 += ls0; l1 += ls1;

        // ---- P fragments (hi/lo) from sacc ----
        unsigned pfh[4][4], pfl[4][4];
        #pragma unroll
        for (int j = 0; j < 4; j++) {
            pack_hilo(sacc[2*j][0],   sacc[2*j][1],   pfh[j][0], pfl[j][0]);
            pack_hilo(sacc[2*j][2],   sacc[2*j][3],   pfh[j][1], pfl[j][1]);
            pack_hilo(sacc[2*j+1][0], sacc[2*j+1][1], pfh[j][2], pfl[j][2]);
            pack_hilo(sacc[2*j+1][2], sacc[2*j+1][3], pfh[j][3], pfl[j][3]);
        }

        // ---- O += P @ V ----
        {
            const int vrow = ((grp & 1) << 3) + li;   // + 16j
            const int vccb = grp >> 1;                // + d
            #pragma unroll
            for (int j = 0; j < 4; j++) {
                unsigned vb2[8][2];
                #pragma unroll
                for (int d = 0; d < 8; d += 2)
                    ldsm4t(vb2[d][0], vb2[d][1], vb2[d+1][0], vb2[d+1][1],
                           smb + swz(VHb, 16*j + vrow, d + vccb));
                #pragma unroll
                for (int nt = 0; nt < 8; nt++) mma_bf16(oacc[nt], pfh[j], vb2[nt]);
                #pragma unroll
                for (int nt = 0; nt < 8; nt++) mma_bf16(oacc[nt], pfl[j], vb2[nt]);
                #pragma unroll
                for (int d = 0; d < 8; d += 2)
                    ldsm4t(vb2[d][0], vb2[d][1], vb2[d+1][0], vb2[d+1][1],
                           smb + swz(VLb, 16*j + vrow, d + vccb));
                #pragma unroll
                for (int nt = 0; nt < 8; nt++) mma_bf16(oacc[nt], pfh[j], vb2[nt]);
            }
        }
    }

    // ---- finalize + write ctx hi/lo ----
    float inv0 = 1.0f / l0, inv1 = 1.0f / l1;
    int r0 = qrow0 + warp * 16 + g;
    int r1 = r0 + 8;
    size_t base0 = (size_t)(b * SEQ + r0) * DMODEL + h * DK;
    size_t base1 = (size_t)(b * SEQ + r1) * DMODEL + h * DK;
    #pragma unroll
    for (int nt = 0; nt < 8; nt++) {
        int col = nt * 8 + 2 * c;
        unsigned hi0, lo0, hi1, lo1;
        pack_hilo(oacc[nt][0] * inv0, oacc[nt][1] * inv0, hi0, lo0);
        pack_hilo(oacc[nt][2] * inv1, oacc[nt][3] * inv1, hi1, lo1);
        *(unsigned*)&Ohi[base0 + col] = hi0;
        *(unsigned*)&Olo[base0 + col] = lo0;
        *(unsigned*)&Ohi[base1 + col] = hi1;
        *(unsigned*)&Olo[base1 + col] = lo1;
    }
}

// ---------------------------------------------------------------------------
// Host launch
// ---------------------------------------------------------------------------
extern "C" void kernel_launch(void* const* d_in, const int* in_sizes, int n_in,
                              void* d_out, int out_size)
{
    const float* x     = (const float*)d_in[0];
    const int*   mask  = (const int*)  d_in[1];
    const float* Wq    = (const float*)d_in[2];
    const float* bq    = (const float*)d_in[3];
    const float* Wk    = (const float*)d_in[4];
    const float* bk    = (const float*)d_in[5];
    const float* Wv    = (const float*)d_in[6];
    const float* bv    = (const float*)d_in[7];
    const float* Wo    = (const float*)d_in[8];
    const float* bo    = (const float*)d_in[9];
    const float* W1    = (const float*)d_in[10];
    const float* b1    = (const float*)d_in[11];
    const float* W2    = (const float*)d_in[12];
    const float* b2    = (const float*)d_in[13];
    const float* ln1_g = (const float*)d_in[14];
    const float* ln1_b = (const float*)d_in[15];
    const float* ln2_g = (const float*)d_in[16];
    const float* ln2_b = (const float*)d_in[17];
    float* out = (float*)d_out;

    float* x1;
    __nv_bfloat16 *hh, *hl, *qh, *ql, *kh, *kl, *vh, *vl, *ctxh, *ctxl, *h2h, *h2l, *ffnh, *ffnl;
    __nv_bfloat16 *wqh,*wql,*wkh,*wkl,*wvh,*wvl,*woh,*wol,*w1h,*w1l,*w2h,*w2l;
    cudaGetSymbolAddress((void**)&x1,  g_x1);
    cudaGetSymbolAddress((void**)&hh,  g_hh);
    cudaGetSymbolAddress((void**)&hl,  g_hl);
    cudaGetSymbolAddress((void**)&qh,  g_qh);  cudaGetSymbolAddress((void**)&ql, g_ql);
    cudaGetSymbolAddress((void**)&kh,  g_kh);  cudaGetSymbolAddress((void**)&kl, g_kl);
    cudaGetSymbolAddress((void**)&vh,  g_vh);  cudaGetSymbolAddress((void**)&vl, g_vl);
    cudaGetSymbolAddress((void**)&ctxh, g_ctxh);
    cudaGetSymbolAddress((void**)&ctxl, g_ctxl);
    cudaGetSymbolAddress((void**)&h2h, g_h2h);
    cudaGetSymbolAddress((void**)&h2l, g_h2l);
    cudaGetSymbolAddress((void**)&ffnh, g_ffnh);
    cudaGetSymbolAddress((void**)&ffnl, g_ffnl);
    cudaGetSymbolAddress((void**)&wqh, g_wqh); cudaGetSymbolAddress((void**)&wql, g_wql);
    cudaGetSymbolAddress((void**)&wkh, g_wkh); cudaGetSymbolAddress((void**)&wkl, g_wkl);
    cudaGetSymbolAddress((void**)&wvh, g_wvh); cudaGetSymbolAddress((void**)&wvl, g_wvl);
    cudaGetSymbolAddress((void**)&woh, g_woh); cudaGetSymbolAddress((void**)&wol, g_wol);
    cudaGetSymbolAddress((void**)&w1h, g_w1h); cudaGetSymbolAddress((void**)&w1l, g_w1l);
    cudaGetSymbolAddress((void**)&w2h, g_w2h); cudaGetSymbolAddress((void**)&w2l, g_w2l);

    cudaFuncSetAttribute(attn_mma, cudaFuncAttributeMaxDynamicSharedMemorySize, ATT_SMEM);

    // 0) weight split+transpose
    dim3 gW(DMODEL/32, DMODEL/32);
    wsplit_kernel<<<gW, 256>>>(Wq, wqh, wql, DMODEL, DMODEL);
    wsplit_kernel<<<gW, 256>>>(Wk, wkh, wkl, DMODEL, DMODEL);
    wsplit_kernel<<<gW, 256>>>(Wv, wvh, wvl, DMODEL, DMODEL);
    wsplit_kernel<<<gW, 256>>>(Wo, woh, wol, DMODEL, DMODEL);
    dim3 gW1(DFF/32, DMODEL/32);
    wsplit_kernel<<<gW1, 256>>>(W1, w1h, w1l, DMODEL, DFF);
    dim3 gW2(DMODEL/32, DFF/32);
    wsplit_kernel<<<gW2, 256>>>(W2, w2h, w2l, DFF, DMODEL);

    // 1) LN1 -> bf16 split
    ln_kernel<<<MROWS, 256>>>(x, ln1_g, ln1_b, hh, hl);

    // 2) QKV projections -> bf16 hi/lo
    dim3 gP(DMODEL/128, MROWS/128);
    mma_gemm<3><<<gP, 256>>>(hh, hl, wqh, wql, bq, nullptr, nullptr, qh, ql, MROWS, DMODEL, DMODEL);
    mma_gemm<3><<<gP, 256>>>(hh, hl, wkh, wkl, bk, nullptr, nullptr, kh, kl, MROWS, DMODEL, DMODEL);
    mma_gemm<3><<<gP, 256>>>(hh, hl, wvh, wvl, bv, nullptr, nullptr, vh, vl, MROWS, DMODEL, DMODEL);

    // 3) tensor-core attention -> ctx bf16 hi/lo
    dim3 gA(SEQ/64, NHEADS, BATCH);
    attn_mma<<<gA, 128, ATT_SMEM>>>(qh, ql, kh, kl, vh, vl, mask, ctxh, ctxl);

    // 4) output projection + residual -> x1 (fp32)
    mma_gemm<1><<<gP, 256>>>(ctxh, ctxl, woh, wol, bo, x, x1, nullptr, nullptr, MROWS, DMODEL, DMODEL);

    // 5) LN2 -> bf16 split
    ln_kernel<<<MROWS, 256>>>(x1, ln2_g, ln2_b, h2h, h2l);

    // 6) FFN up + GELU -> ffn bf16 split
    dim3 gF1(DFF/128, MROWS/128);
    mma_gemm<2><<<gF1, 256>>>(h2h, h2l, w1h, w1l, b1, nullptr, nullptr, ffnh, ffnl, MROWS, DFF, DMODEL);

    // 7) FFN down + residual -> out (fp32)
    dim3 gF2(DMODEL/128, MROWS/128);
    mma_gemm<1><<<gF2, 256>>>(ffnh, ffnl, w2h, w2l, b2, x1, out, nullptr, nullptr, MROWS, DMODEL, DFF);
}